// round 2
// baseline (speedup 1.0000x reference)
#include <cuda_runtime.h>
#include <cstdint>

// ---------------------------------------------------------------------------
// YOLO post-process: score -> exact top-1024 (value desc, index asc) ->
// class-agnostic greedy NMS -> dets/valid/feats assembly.
//
// Output layout (float32), total 58200 elements:
//   [0,            28800)  dets  (16, 300, 6): x1,y1,x2,y2,conf,cls
//   [28800,        33600)  valid (16, 300) as 0.0/1.0
//   [33600,        58200)  feats (300, 82) for batch 0
// ---------------------------------------------------------------------------

#define BATCH   16
#define NBOX    25200
#define NCLS    80
#define KC      1024
#define MAXDET  300
#define CONF_T  0.4f
#define IOU_T   0.25f

typedef unsigned int       u32;
typedef unsigned long long u64;

// --------------------------- device scratch --------------------------------
__device__ u32    g_key[BATCH * NBOX];        // conf bits if candidate else 0
__device__ int    g_cls[BATCH * NBOX];        // argmax class
__device__ float4 g_boxes[BATCH * KC];        // xyxy of selected candidates
__device__ float  g_vals[BATCH * KC];         // conf (or -1)
__device__ int    g_clsk[BATCH * KC];
__device__ int    g_valid0[BATCH * KC];
__device__ u64    g_mask[BATCH * KC * 16];    // suppress bitmask words

// --------------------------- K1: score / argmax ----------------------------
// One warp per box. conf = max_c( cls_c * obj ), ties -> lowest class index
// (matches jnp.argmax). Non-fused multiply to match XLA elementwise rounding.
__global__ __launch_bounds__(256) void k1_score(const float* __restrict__ pred)
{
    int gt   = blockIdx.x * blockDim.x + threadIdx.x;
    int w    = gt >> 5;
    int lane = gt & 31;
    if (w >= BATCH * NBOX) return;

    const float* row = pred + (long long)w * 85;
    float obj = __ldg(row + 4);

    float best = -1e30f;
    int   bi   = 0;
    #pragma unroll
    for (int c0 = 0; c0 < NCLS; c0 += 32) {
        int c = c0 + lane;
        if (c < NCLS) {
            float s = __fmul_rn(__ldg(row + 5 + c), obj);
            if (s > best) { best = s; bi = c; }
        }
    }
    // warp reduce: max value, tie -> lower index
    for (int off = 16; off; off >>= 1) {
        float ov = __shfl_down_sync(0xffffffffu, best, off);
        int   oi = __shfl_down_sync(0xffffffffu, bi, off);
        if (ov > best || (ov == best && oi < bi)) { best = ov; bi = oi; }
    }
    if (lane == 0) {
        bool cand = (obj > CONF_T) && (best > CONF_T);
        g_key[w] = cand ? __float_as_uint(best) : 0u;
        g_cls[w] = bi;
    }
}

// --------------------------- K2: exact top-1024 -----------------------------
// Per-batch radix-select on 64-bit composite key (conf_bits<<32)|~n (unique
// per element, orders by value desc then index asc, exactly like lax.top_k).
// 8-bit digits MSB->LSB; prefix matching done via masked compare (no >=64
// shifts). Then collect the 1024 keys >= threshold, bitonic-sort descending,
// and gather boxes (xywh->xyxy with non-fused ops).
__global__ __launch_bounds__(1024) void k2_topk(const float* __restrict__ pred)
{
    int b   = blockIdx.x;
    int tid = threadIdx.x;

    __shared__ u32 hist[256];
    __shared__ u64 sel[KC];
    __shared__ int cnt;
    __shared__ u64 sh_thresh;
    __shared__ int sh_want;

    const u32* keys = g_key + b * NBOX;

    // thresh holds the known high digits (low digits zero); mask selects them.
    u64 thresh = 0, pmask = 0;
    int want = KC;
    for (int pass = 7; pass >= 0; --pass) {
        int sh = pass * 8;
        if (tid < 256) hist[tid] = 0;
        __syncthreads();
        for (int n = tid; n < NBOX; n += 1024) {
            u64 k = ((u64)keys[n] << 32) | (u32)(~n);
            if ((k & pmask) == thresh)
                atomicAdd(&hist[(unsigned)(k >> sh) & 0xFFu], 1u);
        }
        __syncthreads();
        if (tid == 0) {
            int w = want;
            int v = 255;
            for (; v > 0; --v) {
                int c = (int)hist[v];
                if (c >= w) break;
                w -= c;
            }
            sh_thresh = thresh | ((u64)(unsigned)v << sh);
            sh_want   = w;
        }
        __syncthreads();
        thresh = sh_thresh;
        want   = sh_want;
        pmask |= (u64)0xFFu << sh;
        __syncthreads();
    }
    u64 T = thresh;   // exact 1024-th largest composite key

    if (tid == 0) cnt = 0;
    __syncthreads();
    for (int n = tid; n < NBOX; n += 1024) {
        u64 k = ((u64)keys[n] << 32) | (u32)(~n);
        if (k >= T) {
            int p = atomicAdd(&cnt, 1);
            if (p < KC) sel[p] = k;
        }
    }
    __syncthreads();
    for (int p = cnt + tid; p < KC; p += 1024) sel[p] = 0;  // safety pad
    __syncthreads();

    // bitonic sort, descending
    for (unsigned kk = 2; kk <= KC; kk <<= 1) {
        for (unsigned j = kk >> 1; j > 0; j >>= 1) {
            unsigned ixj = (unsigned)tid ^ j;
            if (ixj > (unsigned)tid) {
                u64 a = sel[tid], bv = sel[ixj];
                bool up = ((tid & kk) == 0);           // descending segment
                if (up ? (a < bv) : (a > bv)) { sel[tid] = bv; sel[ixj] = a; }
            }
            __syncthreads();
        }
    }

    // decode + gather
    u64 k  = sel[tid];
    u32 fb = (u32)(k >> 32);
    int n  = (int)(~(u32)k);
    float val = fb ? __uint_as_float(fb) : -1.0f;

    float4 box = make_float4(0.f, 0.f, 0.f, 0.f);
    int cls = 0;
    if (n >= 0 && n < NBOX) {
        const float* row = pred + ((long long)b * NBOX + n) * 85;
        float cx = row[0], cy = row[1], wd = row[2], ht = row[3];
        float hw = __fmul_rn(wd, 0.5f);
        float hh = __fmul_rn(ht, 0.5f);
        box.x = __fsub_rn(cx, hw);
        box.y = __fsub_rn(cy, hh);
        box.z = __fadd_rn(cx, hw);
        box.w = __fadd_rn(cy, hh);
        cls = g_cls[b * NBOX + n];
    }
    g_boxes[b * KC + tid]  = box;
    g_vals[b * KC + tid]   = val;
    g_clsk[b * KC + tid]   = cls;
    g_valid0[b * KC + tid] = (val > CONF_T) ? 1 : 0;
}

// --------------------------- K3: IoU suppress bitmask -----------------------
// grid (jblk=16, iblk=16, b=16), 64 threads: thread = row i inside iblk,
// computes one u64 word of (j > i && iou > IOU_T). All arithmetic non-fused
// and in the reference's exact op order so comparisons are bit-identical.
__global__ __launch_bounds__(64) void k3_mask()
{
    int b  = blockIdx.z;
    int ib = blockIdx.y;
    int jb = blockIdx.x;
    int t  = threadIdx.x;

    __shared__ float4 jbox[64];
    __shared__ float  jarea[64];

    float4 bj = g_boxes[b * KC + jb * 64 + t];
    jbox[t]  = bj;
    jarea[t] = __fmul_rn(__fsub_rn(bj.z, bj.x), __fsub_rn(bj.w, bj.y));
    __syncthreads();

    int i = ib * 64 + t;
    float4 a = g_boxes[b * KC + i];
    float aa = __fmul_rn(__fsub_rn(a.z, a.x), __fsub_rn(a.w, a.y));

    u64 m = 0;
    int jbase = jb * 64;
    #pragma unroll 8
    for (int jj = 0; jj < 64; ++jj) {
        int jg = jbase + jj;
        if (jg > i) {
            float4 bb  = jbox[jj];
            float ltx  = fmaxf(a.x, bb.x);
            float lty  = fmaxf(a.y, bb.y);
            float rbx  = fminf(a.z, bb.z);
            float rby  = fminf(a.w, bb.w);
            float ww   = fmaxf(__fsub_rn(rbx, ltx), 0.0f);
            float hh   = fmaxf(__fsub_rn(rby, lty), 0.0f);
            float inter = __fmul_rn(ww, hh);
            float denom = __fadd_rn(__fsub_rn(__fadd_rn(aa, jarea[jj]), inter), 1e-9f);
            float iou   = __fdiv_rn(inter, denom);
            if (iou > IOU_T) m |= (1ull << jj);
        }
    }
    g_mask[(b * KC + i) * 16 + jb] = m;
}

// --------------------------- K4: greedy NMS + assembly ----------------------
// One block (1024 thr) per batch. Warp 0 runs the serial scan: lanes 0..15
// own the 16 remv words; mask rows prefetched 8 deep into a register ring so
// L2 latency stays off the serial shfl chain. Then block-wide scan produces
// the stable partition (kept first, original order) and writes outputs.
__global__ __launch_bounds__(1024) void k4_nms(const int* __restrict__ imgsz,
                                               float* __restrict__ out)
{
    int b   = blockIdx.x;
    int tid = threadIdx.x;

    __shared__ int keep_s[KC];
    __shared__ int scan_s[KC];
    __shared__ int v0_s[KC];

    v0_s[tid] = g_valid0[b * KC + tid];
    __syncthreads();

    if (tid < 32) {
        int lane = tid;
        const u64* mrow = g_mask + (long long)b * KC * 16 + lane;
        u64 remv = 0;
        u64 buf[8];
        #pragma unroll
        for (int t = 0; t < 8; ++t)
            buf[t] = (lane < 16) ? mrow[t * 16] : 0ull;

        for (int ii = 0; ii < KC; ii += 8) {
            #pragma unroll
            for (int t = 0; t < 8; ++t) {
                int i = ii + t;
                u64 m = buf[t];
                int nx = i + 8;
                buf[t] = (nx < KC && lane < 16) ? mrow[nx * 16] : 0ull;

                int owner = i >> 6;
                unsigned aliveOwn = 1u ^ (unsigned)((remv >> (i & 63)) & 1ull);
                unsigned alive = __shfl_sync(0xffffffffu, aliveOwn, owner);
                int kp = (alive && v0_s[i]) ? 1 : 0;
                if (lane == 0) keep_s[i] = kp;
                if (kp) remv |= m;
            }
        }
    }
    __syncthreads();

    // inclusive Hillis-Steele scan over keep flags
    scan_s[tid] = keep_s[tid];
    __syncthreads();
    for (int off = 1; off < KC; off <<= 1) {
        int v = (tid >= off) ? scan_s[tid - off] : 0;
        __syncthreads();
        scan_s[tid] += v;
        __syncthreads();
    }
    int nkeep = scan_s[KC - 1];
    int rank  = scan_s[tid] - keep_s[tid];

    // img_size may arrive as int32/int64-LE or float32; decode robustly.
    int iv = imgsz ? imgsz[0] : 640;
    float img = (iv > 0 && iv < 1000000) ? (float)iv : __int_as_float(iv);
    float scale = __fdiv_rn(1.0f, img);

    float* dets   = out;
    float* validf = out + BATCH * MAXDET * 6;
    float* feats  = out + BATCH * MAXDET * 6 + BATCH * MAXDET;

    if (keep_s[tid] && rank < MAXDET) {
        int p = rank;
        float4 bx = g_boxes[b * KC + tid];
        float  val = g_vals[b * KC + tid];
        int    cls = g_clsk[b * KC + tid];
        float* d = dets + (b * MAXDET + p) * 6;
        d[0] = bx.x; d[1] = bx.y; d[2] = bx.z; d[3] = bx.w;
        d[4] = val;  d[5] = (float)cls;
        validf[b * MAXDET + p] = 1.0f;
        if (b == 0) {
            float cxv = __fmul_rn(__fmul_rn(__fadd_rn(bx.x, bx.z), 0.5f), scale);
            float cyv = __fmul_rn(__fmul_rn(__fadd_rn(bx.y, bx.w), 0.5f), scale);
            float* f = feats + p * 82;
            f[0] = cxv;
            f[1] = cyv;
            for (int j = 0; j < NCLS; ++j) f[2 + j] = (j == cls) ? 1.0f : 0.0f;
        }
    }
    if (tid < MAXDET && tid >= nkeep) {
        int p = tid;
        float* d = dets + (b * MAXDET + p) * 6;
        d[0] = 0.f; d[1] = 0.f; d[2] = 0.f; d[3] = 0.f; d[4] = 0.f; d[5] = 0.f;
        validf[b * MAXDET + p] = 0.0f;
        if (b == 0) {
            float* f = feats + p * 82;
            for (int j = 0; j < 82; ++j) f[j] = 0.0f;
        }
    }
}

// --------------------------- launch -----------------------------------------
extern "C" void kernel_launch(void* const* d_in, const int* in_sizes, int n_in,
                              void* d_out, int out_size)
{
    const float* pred  = (const float*)d_in[0];
    const int*   imgsz = (n_in >= 2) ? (const int*)d_in[1] : nullptr;
    float* out = (float*)d_out;

    {
        long long totalThreads = (long long)BATCH * NBOX * 32;
        int threads = 256;
        int blocks  = (int)((totalThreads + threads - 1) / threads);
        k1_score<<<blocks, threads>>>(pred);
    }
    k2_topk<<<BATCH, 1024>>>(pred);
    k3_mask<<<dim3(16, 16, BATCH), 64>>>();
    k4_nms<<<BATCH, 1024>>>(imgsz, out);
}

// round 3
// speedup vs baseline: 1.0165x; 1.0165x over previous
#include <cuda_runtime.h>
#include <cstdint>

// ---------------------------------------------------------------------------
// YOLO post-process: score -> exact top-1024 (value desc, index asc) ->
// on-demand greedy NMS (IoU only vs kept boxes) -> dets/valid/feats assembly.
//
// Output layout (float32), total 58200 elements:
//   [0,     28800)  dets  (16, 300, 6): x1,y1,x2,y2,conf,cls
//   [28800, 33600)  valid (16, 300) as 0.0/1.0
//   [33600, 58200)  feats (300, 82) for batch 0
// ---------------------------------------------------------------------------

#define BATCH   16
#define NBOX    25200
#define NCLS    80
#define KC      1024
#define MAXDET  300
#define CONF_T  0.4f

typedef unsigned int       u32;
typedef unsigned long long u64;

// --------------------------- device scratch --------------------------------
__device__ u32    g_key[BATCH * NBOX];        // conf bits if candidate else 0
__device__ int    g_cls[BATCH * NBOX];        // argmax class
__device__ float4 g_boxes[BATCH * KC];        // xyxy of selected candidates
__device__ float  g_vals[BATCH * KC];         // conf (or -1)
__device__ int    g_clsk[BATCH * KC];
__device__ int    g_valid0[BATCH * KC];

// --------------------------- K1: score / argmax ----------------------------
// One warp per box. conf = max_c( cls_c * obj ), ties -> lowest class index
// (matches jnp.argmax). Non-fused multiply to match XLA elementwise rounding.
__global__ __launch_bounds__(256) void k1_score(const float* __restrict__ pred)
{
    int gt   = blockIdx.x * blockDim.x + threadIdx.x;
    int w    = gt >> 5;
    int lane = gt & 31;
    if (w >= BATCH * NBOX) return;

    const float* row = pred + (long long)w * 85;
    float obj = __ldg(row + 4);

    float best = -1e30f;
    int   bi   = 0;
    #pragma unroll
    for (int c0 = 0; c0 < NCLS; c0 += 32) {
        int c = c0 + lane;
        if (c < NCLS) {
            float s = __fmul_rn(__ldg(row + 5 + c), obj);
            if (s > best) { best = s; bi = c; }
        }
    }
    for (int off = 16; off; off >>= 1) {
        float ov = __shfl_down_sync(0xffffffffu, best, off);
        int   oi = __shfl_down_sync(0xffffffffu, bi, off);
        if (ov > best || (ov == best && oi < bi)) { best = ov; bi = oi; }
    }
    if (lane == 0) {
        bool cand = (obj > CONF_T) && (best > CONF_T);
        g_key[w] = cand ? __float_as_uint(best) : 0u;
        g_cls[w] = bi;
    }
}

// --------------------------- K2: exact top-1024 -----------------------------
// Keys staged in dynamic shared memory once; 8-pass radix-select on 64-bit
// composite key (conf_bits<<32)|~n (orders by value desc, index asc like
// lax.top_k). Collect >= threshold, bitonic sort desc, gather boxes.
#define K2_KEYS_OFF 0
#define K2_SEL_OFF  100800           // 25200*4, 8-aligned
#define K2_HIST_OFF (K2_SEL_OFF + KC * 8)
#define K2_SMEM     (K2_HIST_OFF + 256 * 4)

__global__ __launch_bounds__(1024) void k2_topk(const float* __restrict__ pred)
{
    extern __shared__ unsigned char dsm[];
    u32* skeys = (u32*)(dsm + K2_KEYS_OFF);
    u64* sel   = (u64*)(dsm + K2_SEL_OFF);
    u32* hist  = (u32*)(dsm + K2_HIST_OFF);

    __shared__ int cnt;
    __shared__ u64 sh_thresh;
    __shared__ int sh_want;

    int b   = blockIdx.x;
    int tid = threadIdx.x;

    const u32* keys = g_key + b * NBOX;
    for (int n = tid; n < NBOX; n += 1024) skeys[n] = keys[n];
    __syncthreads();

    u64 thresh = 0, pmask = 0;
    int want = KC;
    for (int pass = 7; pass >= 0; --pass) {
        int sh = pass * 8;
        if (tid < 256) hist[tid] = 0;
        __syncthreads();
        for (int n = tid; n < NBOX; n += 1024) {
            u64 k = ((u64)skeys[n] << 32) | (u32)(~n);
            if ((k & pmask) == thresh)
                atomicAdd(&hist[(unsigned)(k >> sh) & 0xFFu], 1u);
        }
        __syncthreads();
        if (tid == 0) {
            int w = want;
            int v = 255;
            for (; v > 0; --v) {
                int c = (int)hist[v];
                if (c >= w) break;
                w -= c;
            }
            sh_thresh = thresh | ((u64)(unsigned)v << sh);
            sh_want   = w;
        }
        __syncthreads();
        thresh = sh_thresh;
        want   = sh_want;
        pmask |= (u64)0xFFu << sh;
        __syncthreads();
    }
    u64 T = thresh;   // exact 1024-th largest composite key

    if (tid == 0) cnt = 0;
    __syncthreads();
    for (int n = tid; n < NBOX; n += 1024) {
        u64 k = ((u64)skeys[n] << 32) | (u32)(~n);
        if (k >= T) {
            int p = atomicAdd(&cnt, 1);
            if (p < KC) sel[p] = k;
        }
    }
    __syncthreads();
    for (int p = cnt + tid; p < KC; p += 1024) sel[p] = 0;  // safety pad
    __syncthreads();

    // bitonic sort, descending
    for (unsigned kk = 2; kk <= KC; kk <<= 1) {
        for (unsigned j = kk >> 1; j > 0; j >>= 1) {
            unsigned ixj = (unsigned)tid ^ j;
            if (ixj > (unsigned)tid) {
                u64 a = sel[tid], bv = sel[ixj];
                bool up = ((tid & kk) == 0);
                if (up ? (a < bv) : (a > bv)) { sel[tid] = bv; sel[ixj] = a; }
            }
            __syncthreads();
        }
    }

    // decode + gather (xywh->xyxy, non-fused to match XLA rounding)
    u64 k  = sel[tid];
    u32 fb = (u32)(k >> 32);
    int n  = (int)(~(u32)k);
    float val = fb ? __uint_as_float(fb) : -1.0f;

    float4 box = make_float4(0.f, 0.f, 0.f, 0.f);
    int cls = 0;
    if (n >= 0 && n < NBOX) {
        const float* row = pred + ((long long)b * NBOX + n) * 85;
        float cx = row[0], cy = row[1], wd = row[2], ht = row[3];
        float hw = __fmul_rn(wd, 0.5f);
        float hh = __fmul_rn(ht, 0.5f);
        box.x = __fsub_rn(cx, hw);
        box.y = __fsub_rn(cy, hh);
        box.z = __fadd_rn(cx, hw);
        box.w = __fadd_rn(cy, hh);
        cls = g_cls[b * NBOX + n];
    }
    g_boxes[b * KC + tid]  = box;
    g_vals[b * KC + tid]   = val;
    g_clsk[b * KC + tid]   = cls;
    g_valid0[b * KC + tid] = (val > CONF_T) ? 1 : 0;
}

// --------------------------- K3: fused greedy NMS + assembly ----------------
// One block (1024 thr) per batch. Warp 0 keeps the alive set as 32 u32 words
// (one per lane) and does ffs/ballot find-next: suppressed/processed boxes
// cost nothing. For each KEPT box, all 1024 threads compute one IoU in
// parallel (exact: division avoided only when provably decidable without it),
// ballot the suppress bits, and warp 0 clears them. Then stable partition +
// output assembly.
__global__ __launch_bounds__(1024) void k3_nms(const int* __restrict__ imgsz,
                                               float* __restrict__ out)
{
    int b    = blockIdx.x;
    int tid  = threadIdx.x;
    int lane = tid & 31;
    int wid  = tid >> 5;

    __shared__ float4  s_box[KC];
    __shared__ float   s_area[KC];
    __shared__ u32     s_valid[32];
    __shared__ u32     s_sup[32];
    __shared__ u32     s_kept[32];
    __shared__ int     s_cur;
    __shared__ int     keep_s[KC];
    __shared__ int     scan_s[KC];

    // stage boxes/areas; build valid bitmask words
    float4 mb  = g_boxes[b * KC + tid];
    float  mar = __fmul_rn(__fsub_rn(mb.z, mb.x), __fsub_rn(mb.w, mb.y));
    s_box[tid]  = mb;
    s_area[tid] = mar;
    int v0 = g_valid0[b * KC + tid];
    u32 vb = __ballot_sync(0xffffffffu, v0 != 0);
    if (lane == 0) s_valid[wid] = vb;
    if (tid < 32) s_sup[tid] = 0;
    __syncthreads();

    u32 remaining = 0, kept = 0;
    if (tid < 32) remaining = s_valid[tid];

    for (;;) {
        if (tid < 32) {
            remaining &= ~s_sup[tid];              // apply previous suppression
            u32 bal = __ballot_sync(0xffffffffu, remaining != 0u);
            int nxt = -1;
            int L = __ffs((int)bal) - 1;           // lowest lane with work
            u32 w = __shfl_sync(0xffffffffu, remaining, L & 31);
            if (bal) {
                int j = __ffs((int)w) - 1;
                nxt = L * 32 + j;
                if (tid == L) {
                    remaining &= ~(1u << j);
                    kept      |=  (1u << j);
                }
            }
            if (tid == 0) s_cur = nxt;
        }
        __syncthreads();
        int i = s_cur;
        if (i < 0) break;

        // IoU of kept box i vs my box, exactly as reference rounding.
        float4 a  = s_box[i];
        float  aa = s_area[i];
        bool sup = false;
        if (tid > i) {
            float ltx = fmaxf(a.x, mb.x);
            float lty = fmaxf(a.y, mb.y);
            float rbx = fminf(a.z, mb.z);
            float rby = fminf(a.w, mb.w);
            float ww  = fmaxf(__fsub_rn(rbx, ltx), 0.0f);
            float hh  = fmaxf(__fsub_rn(rby, lty), 0.0f);
            float inter = __fmul_rn(ww, hh);
            float denom = __fadd_rn(__fsub_rn(__fadd_rn(aa, mar), inter), 1e-9f);
            // 4*inter <= denom  =>  exact I/D <= 0.25  =>  fdiv_rn <= 0.25.
            if (__fmul_rn(inter, 4.0f) > denom)
                sup = (__fdiv_rn(inter, denom) > 0.25f);
        }
        u32 sb = __ballot_sync(0xffffffffu, sup);
        if (lane == 0) s_sup[wid] = sb;
        __syncthreads();
    }

    if (tid < 32) s_kept[tid] = kept;
    __syncthreads();

    int kp = (int)((s_kept[wid] >> lane) & 1u);
    keep_s[tid] = kp;

    // inclusive Hillis-Steele scan over keep flags
    scan_s[tid] = kp;
    __syncthreads();
    for (int off = 1; off < KC; off <<= 1) {
        int v = (tid >= off) ? scan_s[tid - off] : 0;
        __syncthreads();
        scan_s[tid] += v;
        __syncthreads();
    }
    int nkeep = scan_s[KC - 1];
    int rank  = scan_s[tid] - kp;

    // img_size may arrive as int32 or float32; decode robustly.
    int iv = imgsz ? imgsz[0] : 640;
    float img = (iv > 0 && iv < 1000000) ? (float)iv : __int_as_float(iv);
    float scale = __fdiv_rn(1.0f, img);

    float* dets   = out;
    float* validf = out + BATCH * MAXDET * 6;
    float* feats  = out + BATCH * MAXDET * 6 + BATCH * MAXDET;

    if (kp && rank < MAXDET) {
        int p = rank;
        float  val = g_vals[b * KC + tid];
        int    cls = g_clsk[b * KC + tid];
        float* d = dets + (b * MAXDET + p) * 6;
        d[0] = mb.x; d[1] = mb.y; d[2] = mb.z; d[3] = mb.w;
        d[4] = val;  d[5] = (float)cls;
        validf[b * MAXDET + p] = 1.0f;
        if (b == 0) {
            float cxv = __fmul_rn(__fmul_rn(__fadd_rn(mb.x, mb.z), 0.5f), scale);
            float cyv = __fmul_rn(__fmul_rn(__fadd_rn(mb.y, mb.w), 0.5f), scale);
            float* f = feats + p * 82;
            f[0] = cxv;
            f[1] = cyv;
            for (int j = 0; j < NCLS; ++j) f[2 + j] = (j == cls) ? 1.0f : 0.0f;
        }
    }
    if (tid < MAXDET && tid >= nkeep) {
        int p = tid;
        float* d = dets + (b * MAXDET + p) * 6;
        d[0] = 0.f; d[1] = 0.f; d[2] = 0.f; d[3] = 0.f; d[4] = 0.f; d[5] = 0.f;
        validf[b * MAXDET + p] = 0.0f;
        if (b == 0) {
            float* f = feats + p * 82;
            for (int j = 0; j < 82; ++j) f[j] = 0.0f;
        }
    }
}

// --------------------------- launch -----------------------------------------
extern "C" void kernel_launch(void* const* d_in, const int* in_sizes, int n_in,
                              void* d_out, int out_size)
{
    const float* pred  = (const float*)d_in[0];
    const int*   imgsz = (n_in >= 2) ? (const int*)d_in[1] : nullptr;
    float* out = (float*)d_out;

    cudaFuncSetAttribute(k2_topk, cudaFuncAttributeMaxDynamicSharedMemorySize,
                         K2_SMEM);

    {
        long long totalThreads = (long long)BATCH * NBOX * 32;
        int threads = 256;
        int blocks  = (int)((totalThreads + threads - 1) / threads);
        k1_score<<<blocks, threads>>>(pred);
    }
    k2_topk<<<BATCH, 1024, K2_SMEM>>>(pred);
    k3_nms<<<BATCH, 1024>>>(imgsz, out);
}

// round 4
// speedup vs baseline: 1.2948x; 1.2738x over previous
#include <cuda_runtime.h>
#include <cstdint>

// ---------------------------------------------------------------------------
// YOLO post-process: score -> exact top-1024 (value desc, index asc) ->
// bitmask NMS (upper-triangle, div-avoiding) + grouped-64 serial scan ->
// dets/valid/feats assembly.
//
// Output layout (float32), total 58200 elements:
//   [0,     28800)  dets  (16, 300, 6): x1,y1,x2,y2,conf,cls
//   [28800, 33600)  valid (16, 300) as 0.0/1.0
//   [33600, 58200)  feats (300, 82) for batch 0
// ---------------------------------------------------------------------------

#define BATCH   16
#define NBOX    25200
#define NCLS    80
#define KC      1024
#define MAXDET  300
#define CONF_T  0.4f

typedef unsigned int       u32;
typedef unsigned long long u64;

// --------------------------- device scratch --------------------------------
__device__ u32    g_key[BATCH * NBOX];        // conf bits if candidate else 0
__device__ int    g_cls[BATCH * NBOX];        // argmax class
__device__ float4 g_boxes[BATCH * KC];        // xyxy of selected candidates
__device__ float  g_vals[BATCH * KC];         // conf (or -1)
__device__ int    g_clsk[BATCH * KC];
__device__ int    g_valid0[BATCH * KC];
__device__ u64    g_mask[BATCH * KC * 16];    // suppress bitmask (upper tri)

// --------------------------- K1: score / argmax ----------------------------
// 64 boxes per 256-thread block. Rows staged coalesced into smem, then
// 4 threads per box each reduce 20 classes (stride 4) from smem, 2-step
// width-4 shuffle combine. conf = max_c(cls_c * obj), ties -> lowest class.
#define K1_BOXES 64
__global__ __launch_bounds__(256) void k1_score(const float* __restrict__ pred)
{
    __shared__ float srow[K1_BOXES * 85];

    int tid = threadIdx.x;
    long long boxBase = (long long)blockIdx.x * K1_BOXES;  // 6300 blocks exact
    const float* gp = pred + boxBase * 85;

    #pragma unroll
    for (int idx = tid; idx < K1_BOXES * 85; idx += 256)
        srow[idx] = gp[idx];
    __syncthreads();

    int bx = tid >> 2;          // box within block
    int s  = tid & 3;           // sub-lane
    const float* row = srow + bx * 85;
    float obj = row[4];

    float best = -1e30f;
    int   bi   = 0;
    #pragma unroll
    for (int j = 0; j < 20; ++j) {
        int c = s + 4 * j;
        float v = __fmul_rn(row[5 + c], obj);
        if (v > best) { best = v; bi = c; }
    }
    // combine 4 lanes: max value, tie -> lower class index
    #pragma unroll
    for (int off = 2; off; off >>= 1) {
        float ov = __shfl_down_sync(0xffffffffu, best, off, 4);
        int   oi = __shfl_down_sync(0xffffffffu, bi, off, 4);
        if (ov > best || (ov == best && oi < bi)) { best = ov; bi = oi; }
    }
    if (s == 0) {
        long long w = boxBase + bx;
        bool cand = (obj > CONF_T) && (best > CONF_T);
        g_key[w] = cand ? __float_as_uint(best) : 0u;
        g_cls[w] = bi;
    }
}

// --------------------------- K2: exact top-1024 -----------------------------
// Keys staged in shared; 8-pass radix-select on composite (conf<<32)|~n.
// Histogram atomics warp-aggregated via match_any (digits are concentrated).
#define K2_KEYS_OFF 0
#define K2_SEL_OFF  100800           // 25200*4, 8-aligned
#define K2_HIST_OFF (K2_SEL_OFF + KC * 8)
#define K2_SMEM     (K2_HIST_OFF + 256 * 4)
#define NBOX_PAD    25600            // 25*1024

__global__ __launch_bounds__(1024) void k2_topk(const float* __restrict__ pred)
{
    extern __shared__ unsigned char dsm[];
    u32* skeys = (u32*)(dsm + K2_KEYS_OFF);
    u64* sel   = (u64*)(dsm + K2_SEL_OFF);
    u32* hist  = (u32*)(dsm + K2_HIST_OFF);

    __shared__ int cnt;
    __shared__ u64 sh_thresh;
    __shared__ int sh_want;

    int b   = blockIdx.x;
    int tid = threadIdx.x;

    const u32* keys = g_key + b * NBOX;
    for (int n = tid; n < NBOX; n += 1024) skeys[n] = keys[n];
    __syncthreads();

    u64 thresh = 0, pmask = 0;
    int want = KC;
    for (int pass = 7; pass >= 0; --pass) {
        int sh = pass * 8;
        if (tid < 256) hist[tid] = 0;
        __syncthreads();
        for (int n0 = 0; n0 < NBOX_PAD; n0 += 1024) {
            int n = n0 + tid;
            unsigned dig = 0xFFFFu;   // sentinel: no contribution
            if (n < NBOX) {
                u64 k = ((u64)skeys[n] << 32) | (u32)(~n);
                if ((k & pmask) == thresh)
                    dig = (unsigned)(k >> sh) & 0xFFu;
            }
            u32 grp = __match_any_sync(0xffffffffu, dig);
            int leader = __ffs((int)grp) - 1;
            if (dig != 0xFFFFu && (int)(tid & 31) == leader)
                atomicAdd(&hist[dig], (u32)__popc((int)grp));
        }
        __syncthreads();
        if (tid == 0) {
            int w = want;
            int v = 255;
            for (; v > 0; --v) {
                int c = (int)hist[v];
                if (c >= w) break;
                w -= c;
            }
            sh_thresh = thresh | ((u64)(unsigned)v << sh);
            sh_want   = w;
        }
        __syncthreads();
        thresh = sh_thresh;
        want   = sh_want;
        pmask |= (u64)0xFFu << sh;
        __syncthreads();
    }
    u64 T = thresh;   // exact 1024-th largest composite key

    if (tid == 0) cnt = 0;
    __syncthreads();
    for (int n = tid; n < NBOX; n += 1024) {
        u64 k = ((u64)skeys[n] << 32) | (u32)(~n);
        if (k >= T) {
            int p = atomicAdd(&cnt, 1);
            if (p < KC) sel[p] = k;
        }
    }
    __syncthreads();
    for (int p = cnt + tid; p < KC; p += 1024) sel[p] = 0;  // safety pad
    __syncthreads();

    // bitonic sort, descending
    for (unsigned kk = 2; kk <= KC; kk <<= 1) {
        for (unsigned j = kk >> 1; j > 0; j >>= 1) {
            unsigned ixj = (unsigned)tid ^ j;
            if (ixj > (unsigned)tid) {
                u64 a = sel[tid], bv = sel[ixj];
                bool up = ((tid & kk) == 0);
                if (up ? (a < bv) : (a > bv)) { sel[tid] = bv; sel[ixj] = a; }
            }
            __syncthreads();
        }
    }

    // decode + gather (xywh->xyxy, non-fused to match XLA rounding)
    u64 k  = sel[tid];
    u32 fb = (u32)(k >> 32);
    int n  = (int)(~(u32)k);
    float val = fb ? __uint_as_float(fb) : -1.0f;

    float4 box = make_float4(0.f, 0.f, 0.f, 0.f);
    int cls = 0;
    if (n >= 0 && n < NBOX) {
        const float* row = pred + ((long long)b * NBOX + n) * 85;
        float cx = row[0], cy = row[1], wd = row[2], ht = row[3];
        float hw = __fmul_rn(wd, 0.5f);
        float hh = __fmul_rn(ht, 0.5f);
        box.x = __fsub_rn(cx, hw);
        box.y = __fsub_rn(cy, hh);
        box.z = __fadd_rn(cx, hw);
        box.w = __fadd_rn(cy, hh);
        cls = g_cls[b * NBOX + n];
    }
    g_boxes[b * KC + tid]  = box;
    g_vals[b * KC + tid]   = val;
    g_clsk[b * KC + tid]   = cls;
    g_valid0[b * KC + tid] = (val > CONF_T) ? 1 : 0;
}

// --------------------------- K3: IoU suppress bitmask (upper tri) -----------
// grid (jblk, iblk, b); blocks with jb < ib exit (their words are never read).
// Division avoided when 4*inter <= denom (=> rn(I/D) <= 0.25 by monotonic
// rounding); otherwise exact __fdiv_rn, identical to the reference.
__global__ __launch_bounds__(64) void k3_mask()
{
    int b  = blockIdx.z;
    int ib = blockIdx.y;
    int jb = blockIdx.x;
    if (jb < ib) return;
    int t  = threadIdx.x;

    __shared__ float4 jbox[64];
    __shared__ float  jarea[64];

    float4 bj = g_boxes[b * KC + jb * 64 + t];
    jbox[t]  = bj;
    jarea[t] = __fmul_rn(__fsub_rn(bj.z, bj.x), __fsub_rn(bj.w, bj.y));
    __syncthreads();

    int i = ib * 64 + t;
    float4 a = g_boxes[b * KC + i];
    float aa = __fmul_rn(__fsub_rn(a.z, a.x), __fsub_rn(a.w, a.y));

    u64 m = 0;
    int jbase = jb * 64;
    #pragma unroll 4
    for (int jj = 0; jj < 64; ++jj) {
        int jg = jbase + jj;
        if (jg > i) {
            float4 bb  = jbox[jj];
            float ltx  = fmaxf(a.x, bb.x);
            float lty  = fmaxf(a.y, bb.y);
            float rbx  = fminf(a.z, bb.z);
            float rby  = fminf(a.w, bb.w);
            float ww   = fmaxf(__fsub_rn(rbx, ltx), 0.0f);
            float hh   = fmaxf(__fsub_rn(rby, lty), 0.0f);
            float inter = __fmul_rn(ww, hh);
            float denom = __fadd_rn(__fsub_rn(__fadd_rn(aa, jarea[jj]), inter), 1e-9f);
            if (__fmul_rn(inter, 4.0f) > denom)
                if (__fdiv_rn(inter, denom) > 0.25f) m |= (1ull << jj);
        }
    }
    g_mask[(b * KC + i) * 16 + jb] = m;
}

// --------------------------- K4: grouped serial scan + assembly -------------
// One 256-thread block per batch. Masks staged to smem. Scan runs in 16
// groups of 64: the serial part is 64 register-level steps by one thread
// (bit-test + OR of the diagonal word); cross-group suppression is OR'd into
// s_rem by all 256 threads in parallel. Ranks via popcount prefix.
#define K4_SMEM (KC * 16 * 8)

__global__ __launch_bounds__(256) void k4_scan(const int* __restrict__ imgsz,
                                               float* __restrict__ out)
{
    extern __shared__ u64 smask[];     // KC*16 words
    __shared__ u64 s_rem[16];
    __shared__ u64 s_keep[16];
    __shared__ u64 s_valid[16];
    __shared__ int s_pref[17];

    int b   = blockIdx.x;
    int tid = threadIdx.x;

    const u64* gm = g_mask + (long long)b * KC * 16;
    for (int i = tid; i < KC * 16; i += 256) smask[i] = gm[i];

    if (tid < 16) { s_rem[tid] = 0; s_valid[tid] = 0; }
    __syncthreads();

    // valid bitmask: each thread contributes a 4-bit nibble via u32 atomicOr
    {
        const int* vp = g_valid0 + b * KC + tid * 4;
        unsigned nib = (vp[0] ? 1u : 0u) | (vp[1] ? 2u : 0u) |
                       (vp[2] ? 4u : 0u) | (vp[3] ? 8u : 0u);
        int word  = tid >> 4;             // u64 index
        int shift = (tid & 15) * 4;       // 0..60, 4-aligned (never straddles)
        u32* half = (u32*)&s_valid[word];
        atomicOr(&half[shift >> 5], nib << (shift & 31));
    }
    __syncthreads();

    for (int blk = 0; blk < 16; ++blk) {
        if (tid == 0) {
            u64 rem  = s_rem[blk];
            u64 vv   = s_valid[blk];
            u64 keep = 0;
            const u64* diag = smask + (blk * 64) * 16 + blk;
            #pragma unroll 8
            for (int i = 0; i < 64; ++i) {
                u64 w = diag[i * 16];
                if (((vv >> i) & 1ull) && !((rem >> i) & 1ull)) {
                    keep |= 1ull << i;
                    rem  |= w;
                }
            }
            s_keep[blk] = keep;
        }
        __syncthreads();
        u64 keep = s_keep[blk];
        if (keep && blk < 15) {
            int w = tid & 15;       // word index
            int g = tid >> 4;       // row group
            if (w > blk) {
                u64 acc = 0;
                #pragma unroll 4
                for (int r = g; r < 64; r += 16)
                    if ((keep >> r) & 1ull)
                        acc |= smask[(blk * 64 + r) * 16 + w];
                if (acc) {
                    u32* half = (u32*)&s_rem[w];
                    u32 lo = (u32)acc, hi = (u32)(acc >> 32);
                    if (lo) atomicOr(&half[0], lo);
                    if (hi) atomicOr(&half[1], hi);
                }
            }
        }
        __syncthreads();
    }

    if (tid == 0) {
        int acc = 0;
        #pragma unroll
        for (int i = 0; i < 16; ++i) { s_pref[i] = acc; acc += __popcll(s_keep[i]); }
        s_pref[16] = acc;
    }
    __syncthreads();
    int nkeep = s_pref[16];

    // img_size may arrive as int32 or float32; decode robustly.
    int iv = imgsz ? imgsz[0] : 640;
    float img = (iv > 0 && iv < 1000000) ? (float)iv : __int_as_float(iv);
    float scale = __fdiv_rn(1.0f, img);

    float* dets   = out;
    float* validf = out + BATCH * MAXDET * 6;
    float* feats  = out + BATCH * MAXDET * 6 + BATCH * MAXDET;

    for (int gi = tid; gi < KC; gi += 256) {
        int gw = gi >> 6, bit = gi & 63;
        u64 kw = s_keep[gw];
        if ((kw >> bit) & 1ull) {
            int rank = s_pref[gw] + __popcll(kw & (((u64)1 << bit) - 1));
            if (rank < MAXDET) {
                float4 bx  = g_boxes[b * KC + gi];
                float  val = g_vals[b * KC + gi];
                int    cls = g_clsk[b * KC + gi];
                float* d = dets + (b * MAXDET + rank) * 6;
                d[0] = bx.x; d[1] = bx.y; d[2] = bx.z; d[3] = bx.w;
                d[4] = val;  d[5] = (float)cls;
                validf[b * MAXDET + rank] = 1.0f;
                if (b == 0) {
                    float cxv = __fmul_rn(__fmul_rn(__fadd_rn(bx.x, bx.z), 0.5f), scale);
                    float cyv = __fmul_rn(__fmul_rn(__fadd_rn(bx.y, bx.w), 0.5f), scale);
                    float* f = feats + rank * 82;
                    f[0] = cxv;
                    f[1] = cyv;
                    for (int j = 0; j < NCLS; ++j) f[2 + j] = (j == cls) ? 1.0f : 0.0f;
                }
            }
        }
    }
    for (int p = tid; p < MAXDET; p += 256) {
        if (p >= nkeep) {
            float* d = dets + (b * MAXDET + p) * 6;
            d[0] = 0.f; d[1] = 0.f; d[2] = 0.f; d[3] = 0.f; d[4] = 0.f; d[5] = 0.f;
            validf[b * MAXDET + p] = 0.0f;
            if (b == 0) {
                float* f = feats + p * 82;
                for (int j = 0; j < 82; ++j) f[j] = 0.0f;
            }
        }
    }
}

// --------------------------- launch -----------------------------------------
extern "C" void kernel_launch(void* const* d_in, const int* in_sizes, int n_in,
                              void* d_out, int out_size)
{
    const float* pred  = (const float*)d_in[0];
    const int*   imgsz = (n_in >= 2) ? (const int*)d_in[1] : nullptr;
    float* out = (float*)d_out;

    cudaFuncSetAttribute(k2_topk, cudaFuncAttributeMaxDynamicSharedMemorySize,
                         K2_SMEM);
    cudaFuncSetAttribute(k4_scan, cudaFuncAttributeMaxDynamicSharedMemorySize,
                         K4_SMEM);

    k1_score<<<(BATCH * NBOX) / K1_BOXES, 256>>>(pred);
    k2_topk<<<BATCH, 1024, K2_SMEM>>>(pred);
    k3_mask<<<dim3(16, 16, BATCH), 64>>>();
    k4_scan<<<BATCH, 256, K4_SMEM>>>(imgsz, out);
}